// round 15
// baseline (speedup 1.0000x reference)
#include <cuda_runtime.h>
#include <cuda_fp16.h>
#include <math.h>
#include <stdint.h>
#include <stddef.h>

#define B_SZ   8
#define NTOK   1024
#define NHEAD  16
#define DHEAD  64
#define DMODEL 1024
#define SCALE  0.125f

#define MK ((size_t)B_SZ * NTOK * DMODEL)
#define QKV_W_N ((size_t)3 * DMODEL * DMODEL)
#define PROJ_W_N ((size_t)DMODEL * DMODEL)
#define HSZ ((size_t)B_SZ * NHEAD * NTOK * DHEAD)

// All operands pre-tiled into 128-row x 64-k SW128-swizzled 16KB blocks.
__device__ __align__(1024) __half g_xh[MK];                 // x rounded
__device__ __align__(1024) __half g_qwh[QKV_W_N];           // weights rounded
__device__ __align__(1024) __half g_pwh[PROJ_W_N];
__device__ __align__(1024) __half g_zh[MK];                 // z rounded
// q/k/v: single fp16. Per (b,h): 8 chunks 128tok x 64d, swizzled.
__device__ __align__(1024) __half g_qh[HSZ];
__device__ __align__(1024) __half g_kh[HSZ];
__device__ __align__(1024) __half g_vh[HSZ];

// ---------------------------------------------------------------------------
// helpers
// ---------------------------------------------------------------------------
__device__ __forceinline__ uint32_t smem_u32(const void* p) {
    return (uint32_t)__cvta_generic_to_shared(p);
}
__device__ __forceinline__ uint32_t swz128(uint32_t b) {   // Swizzle<3,4,3>
    return b ^ ((b >> 3) & 0x70);
}
__device__ __forceinline__ void bulkcp(uint32_t dst, const void* src, uint32_t bytes,
                                       uint32_t mbar) {
    asm volatile(
        "cp.async.bulk.shared::cta.global.mbarrier::complete_tx::bytes [%0], [%1], %2, [%3];"
        :: "r"(dst), "l"(src), "r"(bytes), "r"(mbar) : "memory");
}
__device__ __forceinline__ void mbar_init(uint32_t mbar, uint32_t cnt) {
    asm volatile("mbarrier.init.shared.b64 [%0], %1;" :: "r"(mbar), "r"(cnt) : "memory");
}
__device__ __forceinline__ void mbar_expect_tx(uint32_t mbar, uint32_t bytes) {
    asm volatile("mbarrier.arrive.expect_tx.shared.b64 _, [%0], %1;"
                 :: "r"(mbar), "r"(bytes) : "memory");
}
__device__ __forceinline__ void mbar_wait(uint32_t mbar, uint32_t phase) {
    asm volatile(
        "{\n\t.reg .pred P;\n\t"
        "W_%=:\n\t"
        "mbarrier.try_wait.parity.acquire.cta.shared::cta.b64 P, [%0], %1, 0x989680;\n\t"
        "@P bra D_%=;\n\t"
        "bra W_%=;\n\t"
        "D_%=:\n\t}"
        :: "r"(mbar), "r"(phase) : "memory");
}
__device__ __forceinline__ void ldsm4(uint32_t& r0, uint32_t& r1, uint32_t& r2, uint32_t& r3,
                                      uint32_t a) {
    asm volatile("ldmatrix.sync.aligned.m8n8.x4.shared.b16 {%0,%1,%2,%3}, [%4];"
                 : "=r"(r0), "=r"(r1), "=r"(r2), "=r"(r3) : "r"(a));
}
__device__ __forceinline__ void ldsm4t(uint32_t& r0, uint32_t& r1, uint32_t& r2, uint32_t& r3,
                                       uint32_t a) {
    asm volatile("ldmatrix.sync.aligned.m8n8.x4.trans.shared.b16 {%0,%1,%2,%3}, [%4];"
                 : "=r"(r0), "=r"(r1), "=r"(r2), "=r"(r3) : "r"(a));
}
__device__ __forceinline__ void mma16816(float* c,
                                         uint32_t a0, uint32_t a1, uint32_t a2, uint32_t a3,
                                         uint32_t b0, uint32_t b1) {
    asm volatile(
        "mma.sync.aligned.m16n8k16.row.col.f32.f16.f16.f32 "
        "{%0,%1,%2,%3},{%4,%5,%6,%7},{%8,%9},{%0,%1,%2,%3};"
        : "+f"(c[0]), "+f"(c[1]), "+f"(c[2]), "+f"(c[3])
        : "r"(a0), "r"(a1), "r"(a2), "r"(a3), "r"(b0), "r"(b1));
}
__device__ __forceinline__ uint32_t hpack(float a, float b) {
    __half2 h = __floats2half2_rn(a, b);
    return *reinterpret_cast<uint32_t*>(&h);
}
__device__ __forceinline__ float redmax4(float v) {
    v = fmaxf(v, __shfl_xor_sync(0xffffffffu, v, 1));
    v = fmaxf(v, __shfl_xor_sync(0xffffffffu, v, 2));
    return v;
}
__device__ __forceinline__ float redsum4(float v) {
    v += __shfl_xor_sync(0xffffffffu, v, 1);
    v += __shfl_xor_sync(0xffffffffu, v, 2);
    return v;
}

// ---------------------------------------------------------------------------
// Coalesced fp32 -> fp16 round into tiled+swizzled 128x64 blocks.
// ---------------------------------------------------------------------------
__global__ __launch_bounds__(256) void round_coal(const float* __restrict__ x,
                                                  const float* __restrict__ qw,
                                                  const float* __restrict__ pw,
                                                  __half* __restrict__ xh,
                                                  __half* __restrict__ qwh,
                                                  __half* __restrict__ pwh)
{
    __shared__ __align__(16) __half stage[8192];

    const int b = blockIdx.x;
    const float* src;
    __half* dst;
    int li;
    if (b < 1024)      { src = x;  dst = xh;  li = b; }
    else if (b < 1408) { src = qw; dst = qwh; li = b - 1024; }
    else               { src = pw; dst = pwh; li = b - 1408; }

    const int rb = li >> 4;
    const int kc = li & 15;
    const int tid = threadIdx.x;

    #pragma unroll
    for (int i = 0; i < 8; i++) {
        int j   = tid + i * 256;
        int row = j >> 4;
        int c4  = j & 15;
        float4 v = reinterpret_cast<const float4*>(src)[(size_t)(rb * 128 + row) * 256
                                                        + kc * 16 + c4];
        uint32_t off = swz128((uint32_t)(row * 128 + c4 * 8));
        __half2 h01 = __floats2half2_rn(v.x, v.y);
        __half2 h23 = __floats2half2_rn(v.z, v.w);
        *(__half2*)((char*)stage + off)     = h01;
        *(__half2*)((char*)stage + off + 4) = h23;
    }
    __syncthreads();

    char* out = (char*)dst + (size_t)li * 16384;
    #pragma unroll
    for (int i = 0; i < 4; i++) {
        int idx = tid + i * 256;
        reinterpret_cast<float4*>(out)[idx] =
            reinterpret_cast<const float4*>(stage)[idx];
    }
}

// ---------------------------------------------------------------------------
// fp16 single-chain GEMM (mma.sync) with ks-level fragment double-buffering.
// CTA 128M x 128N, K-chunks of 64, 2-stage bulk pipeline, occupancy 2.
// ---------------------------------------------------------------------------
template <int EPI>
__global__ __launch_bounds__(256, 2) void blk_gemm(const __half* __restrict__ Ah,
                                                   const __half* __restrict__ Wh,
                                                   const float* __restrict__ bias,
                                                   float* __restrict__ out)
{
    __shared__ __align__(16) uint64_t mbar[2];
    extern __shared__ __align__(128) char dyn[];

    const int tid  = threadIdx.x;
    const int lane = tid & 31;
    const int warp = tid >> 5;
    const int wm   = warp >> 2;
    const int wn   = warp & 3;
    const int mb   = blockIdx.y;
    const int nb   = blockIdx.x;

    const uint32_t dynb = smem_u32(dyn);
    const uint32_t fullb[2] = {smem_u32(&mbar[0]), smem_u32(&mbar[1])};

    if (tid == 0) { mbar_init(fullb[0], 1); mbar_init(fullb[1], 1); }
    __syncthreads();

    const char* pAh = (const char*)Ah + (size_t)mb * 16 * 16384;
    const char* pWh = (const char*)Wh + (size_t)nb * 16 * 16384;

    auto load_chunk = [&](int s, int c) {
        uint32_t st = dynb + (uint32_t)s * 32768u;
        uint32_t fb = fullb[s];
        mbar_expect_tx(fb, 32768u);
        bulkcp(st,          pAh + (size_t)c * 16384, 16384, fb);
        bulkcp(st + 16384u, pWh + (size_t)c * 16384, 16384, fb);
    };

    if (tid == 0) { load_chunk(0, 0); load_chunk(1, 1); }

    float acc[4][4][4] = {};

    const int a_row  = wm * 64 + (lane & 15);
    const int a_koff = (lane >> 4) << 3;
    const int b_n    = wn * 32 + (lane & 7) + ((lane >> 4) << 3);
    const int b_koff = ((lane >> 3) & 1) << 3;

    uint32_t af[2][4][4];   // [buf][mt][frag]
    uint32_t bf[2][4][2];   // [buf][nt][frag]

    int fph[2] = {0, 0};

    for (int c = 0; c < 16; c++) {
        int s = c & 1;
        mbar_wait(fullb[s], fph[s]); fph[s] ^= 1;
        uint32_t stb = dynb + (uint32_t)s * 32768u;

        // load fragments for ks=0 into buffer 0
        {
            uint32_t swb = swz128((uint32_t)(b_n * 128 + b_koff * 2));
            uint32_t r0, r1, r2, r3;
            ldsm4(r0, r1, r2, r3, stb + 16384u + swb);
            bf[0][0][0] = r0; bf[0][0][1] = r1; bf[0][1][0] = r2; bf[0][1][1] = r3;
            uint32_t swb2 = swz128((uint32_t)((b_n + 16) * 128 + b_koff * 2));
            ldsm4(r0, r1, r2, r3, stb + 16384u + swb2);
            bf[0][2][0] = r0; bf[0][2][1] = r1; bf[0][3][0] = r2; bf[0][3][1] = r3;
            #pragma unroll
            for (int mt = 0; mt < 4; mt++) {
                uint32_t swa = swz128((uint32_t)((a_row + mt * 16) * 128 + a_koff * 2));
                ldsm4(af[0][mt][0], af[0][mt][1], af[0][mt][2], af[0][mt][3], stb + swa);
            }
        }

        #pragma unroll
        for (int ki = 0; ki < 4; ki++) {
            int cur = ki & 1;
            int nxt = cur ^ 1;
            if (ki < 3) {
                int ks = (ki + 1) * 16;
                uint32_t r0, r1, r2, r3;
                uint32_t swb = swz128((uint32_t)(b_n * 128 + (ks + b_koff) * 2));
                ldsm4(r0, r1, r2, r3, stb + 16384u + swb);
                bf[nxt][0][0] = r0; bf[nxt][0][1] = r1;
                bf[nxt][1][0] = r2; bf[nxt][1][1] = r3;
                uint32_t swb2 = swz128((uint32_t)((b_n + 16) * 128 + (ks + b_koff) * 2));
                ldsm4(r0, r1, r2, r3, stb + 16384u + swb2);
                bf[nxt][2][0] = r0; bf[nxt][2][1] = r1;
                bf[nxt][3][0] = r2; bf[nxt][3][1] = r3;
                #pragma unroll
                for (int mt = 0; mt < 4; mt++) {
                    uint32_t swa = swz128((uint32_t)((a_row + mt * 16) * 128 + (ks + a_koff) * 2));
                    ldsm4(af[nxt][mt][0], af[nxt][mt][1], af[nxt][mt][2], af[nxt][mt][3],
                          stb + swa);
                }
            }
            #pragma unroll
            for (int mt = 0; mt < 4; mt++)
                #pragma unroll
                for (int nt = 0; nt < 4; nt++)
                    mma16816(acc[mt][nt], af[cur][mt][0], af[cur][mt][1],
                             af[cur][mt][2], af[cur][mt][3],
                             bf[cur][nt][0], bf[cur][nt][1]);
        }
        __syncthreads();
        if (c + 2 < 16 && tid == 0) load_chunk(s, c + 2);
    }

    // epilogue
    const int row0 = mb * 128;
    const int col0 = nb * 128;
    const int r    = lane >> 2;
    const int cq   = (lane & 3) * 2;
    #pragma unroll
    for (int mt = 0; mt < 4; mt++) {
        int m0 = row0 + wm * 64 + mt * 16 + r;
        #pragma unroll
        for (int nt = 0; nt < 4; nt++) {
            int n = col0 + wn * 32 + nt * 8 + cq;
            float b0 = bias[n], b1 = bias[n + 1];
            float v00 = acc[mt][nt][0] + b0, v01 = acc[mt][nt][1] + b1;
            float v10 = acc[mt][nt][2] + b0, v11 = acc[mt][nt][3] + b1;
            if (EPI == 0) {
                #pragma unroll
                for (int e = 0; e < 2; e++) {
                    int m = m0 + e * 8;
                    float va = e ? v10 : v00;
                    float vb = e ? v11 : v01;
                    int b    = m >> 10, t = m & 1023;
                    int part = n >> 10, hc = n & 1023;
                    int h = hc >> 6, hd = hc & 63;
                    size_t cbase = ((size_t)((b * NHEAD + h) * 8 + (t >> 7))) * 16384;
                    uint32_t sw = swz128((uint32_t)(((t & 127) << 7) + hd * 2));
                    char* dst;
                    if (part == 0) { va *= SCALE; vb *= SCALE; dst = (char*)g_qh; }
                    else if (part == 1) dst = (char*)g_kh;
                    else                dst = (char*)g_vh;
                    *(__half2*)(dst + cbase + sw) = __floats2half2_rn(va, vb);
                }
            } else {
                *(float2*)&out[(size_t)m0 * DMODEL + n]       = make_float2(v00, v01);
                *(float2*)&out[(size_t)(m0 + 8) * DMODEL + n] = make_float2(v10, v11);
            }
        }
    }
}

// ---------------------------------------------------------------------------
// fp16 flash attention, fully single-precision fp16 operands (unchanged).
// smem: Q@0 (16KB) | stages @16384 + s*32768: Kh(16KB)|Vh(16KB). 81920 B.
// ---------------------------------------------------------------------------
__global__ __launch_bounds__(256, 2) void mma_attn()
{
    __shared__ __align__(16) uint64_t abar[3];
    extern __shared__ __align__(128) char dyn[];

    const int qb = blockIdx.x;
    const int bh = blockIdx.y;
    const int tid  = threadIdx.x;
    const int lane = tid & 31;
    const int w    = tid >> 5;

    const uint32_t dynb = smem_u32(dyn);
    const uint32_t qbar = smem_u32(&abar[0]);
    const uint32_t fullb[2] = {smem_u32(&abar[1]), smem_u32(&abar[2])};

    if (tid == 0) {
        mbar_init(qbar, 1);
        mbar_init(fullb[0], 1);
        mbar_init(fullb[1], 1);
    }
    __syncthreads();

    const size_t hbase = (size_t)bh * 8;

    auto load_kv = [&](int s, int t) {
        uint32_t st = dynb + 16384u + (uint32_t)s * 32768u;
        uint32_t fb = fullb[s];
        size_t cb = (hbase + t) * 16384;
        mbar_expect_tx(fb, 32768u);
        bulkcp(st,          (char*)g_kh + cb, 16384, fb);
        bulkcp(st + 16384u, (char*)g_vh + cb, 16384, fb);
    };

    if (tid == 0) {
        size_t qcb = (hbase + qb) * 16384;
        mbar_expect_tx(qbar, 16384u);
        bulkcp(dynb, (char*)g_qh + qcb, 16384, qbar);
        load_kv(0, 0);
        load_kv(1, 1);
    }

    const int k_nloc = (lane & 7) + ((lane >> 4) << 3);
    const int k_koff = ((lane >> 3) & 1) << 3;
    const int v_krl  = (lane & 7) + (((lane >> 3) & 1) << 3);
    const int v_dc   = (lane >> 4) << 3;
    const int qrow   = w * 16 + (lane & 15);
    const int qoff   = (lane >> 4) << 3;

    uint32_t qf[4][4];
    mbar_wait(qbar, 0);
    #pragma unroll
    for (int kk = 0; kk < 4; kk++) {
        uint32_t qsw = swz128((uint32_t)(qrow * 128 + (kk * 16 + qoff) * 2));
        ldsm4(qf[kk][0], qf[kk][1], qf[kk][2], qf[kk][3], dynb + qsw);
    }

    float O[8][4] = {};
    float rm0 = -INFINITY, rm1 = -INFINITY, rl0 = 0.f, rl1 = 0.f;
    int fph[2] = {0, 0};

    for (int t = 0; t < 8; t++) {
        int s = t & 1;
        mbar_wait(fullb[s], fph[s]); fph[s] ^= 1;
        uint32_t stb = dynb + 16384u + (uint32_t)s * 32768u;

        float sa[16][4] = {};
        #pragma unroll
        for (int kk = 0; kk < 4; kk++) {
            #pragma unroll
            for (int p = 0; p < 8; p++) {
                uint32_t sw = swz128((uint32_t)((k_nloc + p * 16) * 128 + (kk * 16 + k_koff) * 2));
                uint32_t r0, r1, r2, r3;
                ldsm4(r0, r1, r2, r3, stb + sw);
                mma16816(sa[2 * p],     qf[kk][0], qf[kk][1], qf[kk][2], qf[kk][3], r0, r1);
                mma16816(sa[2 * p + 1], qf[kk][0], qf[kk][1], qf[kk][2], qf[kk][3], r2, r3);
            }
        }

        float mx0 = -INFINITY, mx1 = -INFINITY;
        #pragma unroll
        for (int j = 0; j < 16; j++) {
            mx0 = fmaxf(mx0, fmaxf(sa[j][0], sa[j][1]));
            mx1 = fmaxf(mx1, fmaxf(sa[j][2], sa[j][3]));
        }
        mx0 = redmax4(mx0); mx1 = redmax4(mx1);
        float nm0 = fmaxf(rm0, mx0), nm1 = fmaxf(rm1, mx1);
        float al0 = __expf(rm0 - nm0), al1 = __expf(rm1 - nm1);
        rm0 = nm0; rm1 = nm1;
        float sm0 = 0.f, sm1 = 0.f;
        #pragma unroll
        for (int j = 0; j < 16; j++) {
            sa[j][0] = __expf(sa[j][0] - nm0);
            sa[j][1] = __expf(sa[j][1] - nm0);
            sa[j][2] = __expf(sa[j][2] - nm1);
            sa[j][3] = __expf(sa[j][3] - nm1);
            sm0 += sa[j][0] + sa[j][1];
            sm1 += sa[j][2] + sa[j][3];
        }
        sm0 = redsum4(sm0); sm1 = redsum4(sm1);
        rl0 = rl0 * al0 + sm0;
        rl1 = rl1 * al1 + sm1;
        #pragma unroll
        for (int nt = 0; nt < 8; nt++) {
            O[nt][0] *= al0; O[nt][1] *= al0;
            O[nt][2] *= al1; O[nt][3] *= al1;
        }

        #pragma unroll
        for (int kk = 0; kk < 8; kk++) {
            uint32_t p0 = hpack(sa[2 * kk][0],     sa[2 * kk][1]);
            uint32_t p1 = hpack(sa[2 * kk][2],     sa[2 * kk][3]);
            uint32_t p2 = hpack(sa[2 * kk + 1][0], sa[2 * kk + 1][1]);
            uint32_t p3 = hpack(sa[2 * kk + 1][2], sa[2 * kk + 1][3]);
            #pragma unroll
            for (int pd = 0; pd < 4; pd++) {
                uint32_t sw = swz128((uint32_t)((v_krl + kk * 16) * 128 + (pd * 16 + v_dc) * 2));
                uint32_t v0, v1, v2, v3;
                ldsm4t(v0, v1, v2, v3, stb + 16384u + sw);
                mma16816(O[2 * pd],     p0, p1, p2, p3, v0, v1);
                mma16816(O[2 * pd + 1], p0, p1, p2, p3, v2, v3);
            }
        }
        __syncthreads();
        if (t + 2 < 8 && tid == 0) load_kv(s, t + 2);
    }

    float inv0 = 1.0f / rl0, inv1 = 1.0f / rl1;
    const int b = bh >> 4, h = bh & 15;
    const int t0 = qb * 128 + w * 16 + (lane >> 2);
    const int cq = (lane & 3) * 2;
    #pragma unroll
    for (int nt = 0; nt < 8; nt++) {
        int kk = nt * 8 + cq;
        #pragma unroll
        for (int e = 0; e < 2; e++) {
            int m = b * NTOK + t0 + e * 8;
            int mb2 = m >> 7, r = m & 127;
            size_t base = ((size_t)mb2 * 16 + h) * 16384;
            uint32_t sw = swz128((uint32_t)(r * 128 + kk * 2));
            float inv = e ? inv1 : inv0;
            __half2 zz = __floats2half2_rn(O[nt][2 * e] * inv, O[nt][2 * e + 1] * inv);
            *(__half2*)((char*)g_zh + base + sw) = zz;
        }
    }
}

// ---------------------------------------------------------------------------
extern "C" void kernel_launch(void* const* d_in, const int* in_sizes, int n_in,
                              void* d_out, int out_size)
{
    const float* x      = (const float*)d_in[0];
    const float* qkv_w  = (const float*)d_in[1];
    const float* qkv_b  = (const float*)d_in[2];
    const float* proj_w = (const float*)d_in[3];
    const float* proj_b = (const float*)d_in[4];
    float* out = (float*)d_out;

    const int M = B_SZ * NTOK;

    cudaFuncSetAttribute(mma_attn, cudaFuncAttributeMaxDynamicSharedMemorySize, 81920);
    cudaFuncSetAttribute(blk_gemm<0>, cudaFuncAttributeMaxDynamicSharedMemorySize, 65536);
    cudaFuncSetAttribute(blk_gemm<1>, cudaFuncAttributeMaxDynamicSharedMemorySize, 65536);

    __half *xh, *qwh, *pwh, *zh;
    cudaGetSymbolAddress((void**)&xh,  g_xh);
    cudaGetSymbolAddress((void**)&qwh, g_qwh);
    cudaGetSymbolAddress((void**)&pwh, g_pwh);
    cudaGetSymbolAddress((void**)&zh,  g_zh);

    dim3 blk(256);

    // 0) coalesced round of x + both weights
    round_coal<<<1536, blk>>>(x, qkv_w, proj_w, xh, qwh, pwh);

    // 1) QKV GEMM -> q/k/v single fp16 swizzled chunks
    blk_gemm<0><<<dim3(3 * DMODEL / 128, M / 128), blk, 65536>>>(
        xh, qwh, qkv_b, nullptr);

    // 2) Flash attention -> z single fp16
    mma_attn<<<dim3(NTOK / 128, B_SZ * NHEAD), blk, 81920>>>();

    // 3) Output projection -> out fp32
    blk_gemm<1><<<dim3(DMODEL / 128, M / 128), blk, 65536>>>(
        zh, pwh, proj_b, out);
}

// round 16
// speedup vs baseline: 1.0543x; 1.0543x over previous
#include <cuda_runtime.h>
#include <cuda_fp16.h>
#include <math.h>
#include <stdint.h>
#include <stddef.h>

#define B_SZ   8
#define NTOK   1024
#define NHEAD  16
#define DHEAD  64
#define DMODEL 1024
// q pre-scaled by SCALE * log2(e) so softmax can use exp2
#define QSCALE 0.18033688f

#define MK ((size_t)B_SZ * NTOK * DMODEL)
#define QKV_W_N ((size_t)3 * DMODEL * DMODEL)
#define PROJ_W_N ((size_t)DMODEL * DMODEL)
#define HSZ ((size_t)B_SZ * NHEAD * NTOK * DHEAD)

// All operands pre-tiled into 128-row x 64-k SW128-swizzled 16KB blocks.
__device__ __align__(1024) __half g_xh[MK];
__device__ __align__(1024) __half g_qwh[QKV_W_N];
__device__ __align__(1024) __half g_pwh[PROJ_W_N];
__device__ __align__(1024) __half g_zh[MK];
__device__ __align__(1024) __half g_qh[HSZ];
__device__ __align__(1024) __half g_kh[HSZ];
__device__ __align__(1024) __half g_vh[HSZ];

// ---------------------------------------------------------------------------
// helpers
// ---------------------------------------------------------------------------
__device__ __forceinline__ uint32_t smem_u32(const void* p) {
    return (uint32_t)__cvta_generic_to_shared(p);
}
__device__ __forceinline__ uint32_t swz128(uint32_t b) {
    return b ^ ((b >> 3) & 0x70);
}
__device__ __forceinline__ void bulkcp(uint32_t dst, const void* src, uint32_t bytes,
                                       uint32_t mbar) {
    asm volatile(
        "cp.async.bulk.shared::cta.global.mbarrier::complete_tx::bytes [%0], [%1], %2, [%3];"
        :: "r"(dst), "l"(src), "r"(bytes), "r"(mbar) : "memory");
}
__device__ __forceinline__ void mbar_init(uint32_t mbar, uint32_t cnt) {
    asm volatile("mbarrier.init.shared.b64 [%0], %1;" :: "r"(mbar), "r"(cnt) : "memory");
}
__device__ __forceinline__ void mbar_expect_tx(uint32_t mbar, uint32_t bytes) {
    asm volatile("mbarrier.arrive.expect_tx.shared.b64 _, [%0], %1;"
                 :: "r"(mbar), "r"(bytes) : "memory");
}
__device__ __forceinline__ void mbar_wait(uint32_t mbar, uint32_t phase) {
    asm volatile(
        "{\n\t.reg .pred P;\n\t"
        "W_%=:\n\t"
        "mbarrier.try_wait.parity.acquire.cta.shared::cta.b64 P, [%0], %1, 0x989680;\n\t"
        "@P bra D_%=;\n\t"
        "bra W_%=;\n\t"
        "D_%=:\n\t}"
        :: "r"(mbar), "r"(phase) : "memory");
}
__device__ __forceinline__ void ldsm4(uint32_t& r0, uint32_t& r1, uint32_t& r2, uint32_t& r3,
                                      uint32_t a) {
    asm volatile("ldmatrix.sync.aligned.m8n8.x4.shared.b16 {%0,%1,%2,%3}, [%4];"
                 : "=r"(r0), "=r"(r1), "=r"(r2), "=r"(r3) : "r"(a));
}
__device__ __forceinline__ void ldsm4t(uint32_t& r0, uint32_t& r1, uint32_t& r2, uint32_t& r3,
                                       uint32_t a) {
    asm volatile("ldmatrix.sync.aligned.m8n8.x4.trans.shared.b16 {%0,%1,%2,%3}, [%4];"
                 : "=r"(r0), "=r"(r1), "=r"(r2), "=r"(r3) : "r"(a));
}
__device__ __forceinline__ void mma16816(float* c,
                                         uint32_t a0, uint32_t a1, uint32_t a2, uint32_t a3,
                                         uint32_t b0, uint32_t b1) {
    asm volatile(
        "mma.sync.aligned.m16n8k16.row.col.f32.f16.f16.f32 "
        "{%0,%1,%2,%3},{%4,%5,%6,%7},{%8,%9},{%0,%1,%2,%3};"
        : "+f"(c[0]), "+f"(c[1]), "+f"(c[2]), "+f"(c[3])
        : "r"(a0), "r"(a1), "r"(a2), "r"(a3), "r"(b0), "r"(b1));
}
__device__ __forceinline__ uint32_t hpack(float a, float b) {
    __half2 h = __floats2half2_rn(a, b);
    return *reinterpret_cast<uint32_t*>(&h);
}
__device__ __forceinline__ float redmax4(float v) {
    v = fmaxf(v, __shfl_xor_sync(0xffffffffu, v, 1));
    v = fmaxf(v, __shfl_xor_sync(0xffffffffu, v, 2));
    return v;
}
__device__ __forceinline__ float redsum4(float v) {
    v += __shfl_xor_sync(0xffffffffu, v, 1);
    v += __shfl_xor_sync(0xffffffffu, v, 2);
    return v;
}

// ---------------------------------------------------------------------------
// Coalesced fp32 -> fp16 round into tiled+swizzled 128x64 blocks.
// ---------------------------------------------------------------------------
__global__ __launch_bounds__(256) void round_coal(const float* __restrict__ x,
                                                  const float* __restrict__ qw,
                                                  const float* __restrict__ pw,
                                                  __half* __restrict__ xh,
                                                  __half* __restrict__ qwh,
                                                  __half* __restrict__ pwh)
{
    __shared__ __align__(16) __half stage[8192];

    const int b = blockIdx.x;
    const float* src;
    __half* dst;
    int li;
    if (b < 1024)      { src = x;  dst = xh;  li = b; }
    else if (b < 1408) { src = qw; dst = qwh; li = b - 1024; }
    else               { src = pw; dst = pwh; li = b - 1408; }

    const int rb = li >> 4;
    const int kc = li & 15;
    const int tid = threadIdx.x;

    #pragma unroll
    for (int i = 0; i < 8; i++) {
        int j   = tid + i * 256;
        int row = j >> 4;
        int c4  = j & 15;
        float4 v = reinterpret_cast<const float4*>(src)[(size_t)(rb * 128 + row) * 256
                                                        + kc * 16 + c4];
        uint32_t off = swz128((uint32_t)(row * 128 + c4 * 8));
        *(__half2*)((char*)stage + off)     = __floats2half2_rn(v.x, v.y);
        *(__half2*)((char*)stage + off + 4) = __floats2half2_rn(v.z, v.w);
    }
    __syncthreads();

    char* out = (char*)dst + (size_t)li * 16384;
    #pragma unroll
    for (int i = 0; i < 4; i++) {
        int idx = tid + i * 256;
        reinterpret_cast<float4*>(out)[idx] =
            reinterpret_cast<const float4*>(stage)[idx];
    }
}

// ---------------------------------------------------------------------------
// fp16 single-chain GEMM (mma.sync): C = Ah @ Wh^T + bias.
// CTA 128M x 128N, K-chunks of 64, 2-stage bulk pipeline, occupancy 2.
// XOR-delta ldsm addressing: per-ks address = base ^ (ki*32).
// ---------------------------------------------------------------------------
template <int EPI>
__global__ __launch_bounds__(256, 2) void blk_gemm(const __half* __restrict__ Ah,
                                                   const __half* __restrict__ Wh,
                                                   const float* __restrict__ bias,
                                                   float* __restrict__ out)
{
    __shared__ __align__(16) uint64_t mbar[2];
    extern __shared__ __align__(128) char dyn[];

    const int tid  = threadIdx.x;
    const int lane = tid & 31;
    const int warp = tid >> 5;
    const int wm   = warp >> 2;
    const int wn   = warp & 3;
    const int mb   = blockIdx.y;
    const int nb   = blockIdx.x;

    const uint32_t dynb = smem_u32(dyn);
    const uint32_t fullb[2] = {smem_u32(&mbar[0]), smem_u32(&mbar[1])};

    if (tid == 0) { mbar_init(fullb[0], 1); mbar_init(fullb[1], 1); }
    __syncthreads();

    const char* pAh = (const char*)Ah + (size_t)mb * 16 * 16384;
    const char* pWh = (const char*)Wh + (size_t)nb * 16 * 16384;

    auto load_chunk = [&](int s, int c) {
        uint32_t st = dynb + (uint32_t)s * 32768u;
        uint32_t fb = fullb[s];
        mbar_expect_tx(fb, 32768u);
        bulkcp(st,          pAh + (size_t)c * 16384, 16384, fb);
        bulkcp(st + 16384u, pWh + (size_t)c * 16384, 16384, fb);
    };

    if (tid == 0) { load_chunk(0, 0); load_chunk(1, 1); }

    float acc[4][4][4] = {};

    const int a_row  = wm * 64 + (lane & 15);
    const int a_kb   = ((lane >> 4) << 3) * 2;     // bytes
    const int b_n    = wn * 32 + (lane & 7) + ((lane >> 4) << 3);
    const int b_kb   = (((lane >> 3) & 1) << 3) * 2;

    // loop-invariant swizzled base offsets (stage-relative)
    uint32_t aoff[4], boff[2];
    #pragma unroll
    for (int mt = 0; mt < 4; mt++) {
        int row = a_row + mt * 16;
        aoff[mt] = (uint32_t)(row * 128 + (a_kb ^ ((row & 7) << 4)));
    }
    #pragma unroll
    for (int p = 0; p < 2; p++) {
        int row = b_n + p * 16;
        boff[p] = 16384u + (uint32_t)(row * 128 + (b_kb ^ ((row & 7) << 4)));
    }

    int fph[2] = {0, 0};

    for (int c = 0; c < 16; c++) {
        int s = c & 1;
        mbar_wait(fullb[s], fph[s]); fph[s] ^= 1;
        uint32_t stb = dynb + (uint32_t)s * 32768u;
        uint32_t ab[4], bb[2];
        #pragma unroll
        for (int mt = 0; mt < 4; mt++) ab[mt] = stb + aoff[mt];
        #pragma unroll
        for (int p = 0; p < 2; p++) bb[p] = stb + boff[p];

        #pragma unroll
        for (int ki = 0; ki < 4; ki++) {
            const uint32_t kd = (uint32_t)(ki * 32);
            uint32_t bh[4][2];
            #pragma unroll
            for (int p = 0; p < 2; p++) {
                uint32_t r0, r1, r2, r3;
                ldsm4(r0, r1, r2, r3, bb[p] ^ kd);
                bh[2 * p][0] = r0; bh[2 * p][1] = r1;
                bh[2 * p + 1][0] = r2; bh[2 * p + 1][1] = r3;
            }
            #pragma unroll
            for (int mt = 0; mt < 4; mt++) {
                uint32_t a0, a1, a2, a3;
                ldsm4(a0, a1, a2, a3, ab[mt] ^ kd);
                #pragma unroll
                for (int nt = 0; nt < 4; nt++)
                    mma16816(acc[mt][nt], a0, a1, a2, a3, bh[nt][0], bh[nt][1]);
            }
        }
        __syncthreads();
        if (c + 2 < 16 && tid == 0) load_chunk(s, c + 2);
    }

    // epilogue
    const int row0 = mb * 128;
    const int col0 = nb * 128;
    const int r    = lane >> 2;
    const int cq   = (lane & 3) * 2;
    #pragma unroll
    for (int mt = 0; mt < 4; mt++) {
        int m0 = row0 + wm * 64 + mt * 16 + r;
        #pragma unroll
        for (int nt = 0; nt < 4; nt++) {
            int n = col0 + wn * 32 + nt * 8 + cq;
            float b0 = bias[n], b1 = bias[n + 1];
            float v00 = acc[mt][nt][0] + b0, v01 = acc[mt][nt][1] + b1;
            float v10 = acc[mt][nt][2] + b0, v11 = acc[mt][nt][3] + b1;
            if (EPI == 0) {
                #pragma unroll
                for (int e = 0; e < 2; e++) {
                    int m = m0 + e * 8;
                    float va = e ? v10 : v00;
                    float vb = e ? v11 : v01;
                    int b    = m >> 10, t = m & 1023;
                    int part = n >> 10, hc = n & 1023;
                    int h = hc >> 6, hd = hc & 63;
                    size_t cbase = ((size_t)((b * NHEAD + h) * 8 + (t >> 7))) * 16384;
                    uint32_t sw = swz128((uint32_t)(((t & 127) << 7) + hd * 2));
                    char* dst;
                    if (part == 0) { va *= QSCALE; vb *= QSCALE; dst = (char*)g_qh; }
                    else if (part == 1) dst = (char*)g_kh;
                    else                dst = (char*)g_vh;
                    *(__half2*)(dst + cbase + sw) = __floats2half2_rn(va, vb);
                }
            } else {
                *(float2*)&out[(size_t)m0 * DMODEL + n]       = make_float2(v00, v01);
                *(float2*)&out[(size_t)(m0 + 8) * DMODEL + n] = make_float2(v10, v11);
            }
        }
    }
}

// ---------------------------------------------------------------------------
// fp16 flash attention (single-chain, log2-domain softmax, XOR-delta addrs).
// smem: Q@0 (16KB) | stages @16384 + s*32768: Kh(16KB)|Vh(16KB). 81920 B.
// ---------------------------------------------------------------------------
__global__ __launch_bounds__(256, 2) void mma_attn()
{
    __shared__ __align__(16) uint64_t abar[3];
    extern __shared__ __align__(128) char dyn[];

    const int qb = blockIdx.x;
    const int bh = blockIdx.y;
    const int tid  = threadIdx.x;
    const int lane = tid & 31;
    const int w    = tid >> 5;

    const uint32_t dynb = smem_u32(dyn);
    const uint32_t qbar = smem_u32(&abar[0]);
    const uint32_t fullb[2] = {smem_u32(&abar[1]), smem_u32(&abar[2])};

    if (tid == 0) {
        mbar_init(qbar, 1);
        mbar_init(fullb[0], 1);
        mbar_init(fullb[1], 1);
    }
    __syncthreads();

    const size_t hbase = (size_t)bh * 8;

    auto load_kv = [&](int s, int t) {
        uint32_t st = dynb + 16384u + (uint32_t)s * 32768u;
        uint32_t fb = fullb[s];
        size_t cb = (hbase + t) * 16384;
        mbar_expect_tx(fb, 32768u);
        bulkcp(st,          (char*)g_kh + cb, 16384, fb);
        bulkcp(st + 16384u, (char*)g_vh + cb, 16384, fb);
    };

    if (tid == 0) {
        size_t qcb = (hbase + qb) * 16384;
        mbar_expect_tx(qbar, 16384u);
        bulkcp(dynb, (char*)g_qh + qcb, 16384, qbar);
        load_kv(0, 0);
        load_kv(1, 1);
    }

    const int k_nloc = (lane & 7) + ((lane >> 4) << 3);
    const int k_kb   = ((((lane >> 3) & 1) << 3) * 2);
    const int v_krl  = (lane & 7) + (((lane >> 3) & 1) << 3);
    const int v_db   = (((lane >> 4) << 3) * 2);
    const int qrow   = w * 16 + (lane & 15);
    const int qoff   = (lane >> 4) << 3;

    // stage-relative swizzled bases
    uint32_t koff[8];
    #pragma unroll
    for (int p = 0; p < 8; p++) {
        int row = k_nloc + p * 16;
        koff[p] = (uint32_t)(row * 128 + (k_kb ^ ((row & 7) << 4)));
    }
    const uint32_t voff0 = 16384u + (uint32_t)(v_krl * 128 + (v_db ^ ((v_krl & 7) << 4)));

    // hoist Q fragments
    uint32_t qf[4][4];
    mbar_wait(qbar, 0);
    #pragma unroll
    for (int kk = 0; kk < 4; kk++) {
        uint32_t qsw = swz128((uint32_t)(qrow * 128 + (kk * 16 + qoff) * 2));
        ldsm4(qf[kk][0], qf[kk][1], qf[kk][2], qf[kk][3], dynb + qsw);
    }

    float O[8][4] = {};
    float rm0 = -INFINITY, rm1 = -INFINITY, rl0 = 0.f, rl1 = 0.f;
    int fph[2] = {0, 0};

    for (int t = 0; t < 8; t++) {
        int s = t & 1;
        mbar_wait(fullb[s], fph[s]); fph[s] ^= 1;
        uint32_t stb = dynb + 16384u + (uint32_t)s * 32768u;

        // ---- S = Q K^T (logits already in log2 domain via QSCALE) ----
        float sa[16][4] = {};
        #pragma unroll
        for (int kk = 0; kk < 4; kk++) {
            const uint32_t kd = (uint32_t)(kk * 32);
            #pragma unroll
            for (int p = 0; p < 8; p++) {
                uint32_t r0, r1, r2, r3;
                ldsm4(r0, r1, r2, r3, (stb + koff[p]) ^ kd);
                mma16816(sa[2 * p],     qf[kk][0], qf[kk][1], qf[kk][2], qf[kk][3], r0, r1);
                mma16816(sa[2 * p + 1], qf[kk][0], qf[kk][1], qf[kk][2], qf[kk][3], r2, r3);
            }
        }

        // ---- online softmax (exp2, warp-local) ----
        float mx0 = -INFINITY, mx1 = -INFINITY;
        #pragma unroll
        for (int j = 0; j < 16; j++) {
            mx0 = fmaxf(mx0, fmaxf(sa[j][0], sa[j][1]));
            mx1 = fmaxf(mx1, fmaxf(sa[j][2], sa[j][3]));
        }
        mx0 = redmax4(mx0); mx1 = redmax4(mx1);
        float nm0 = fmaxf(rm0, mx0), nm1 = fmaxf(rm1, mx1);
        float al0 = exp2f(rm0 - nm0), al1 = exp2f(rm1 - nm1);
        rm0 = nm0; rm1 = nm1;
        float sm0 = 0.f, sm1 = 0.f;
        #pragma unroll
        for (int j = 0; j < 16; j++) {
            sa[j][0] = exp2f(sa[j][0] - nm0);
            sa[j][1] = exp2f(sa[j][1] - nm0);
            sa[j][2] = exp2f(sa[j][2] - nm1);
            sa[j][3] = exp2f(sa[j][3] - nm1);
            sm0 += sa[j][0] + sa[j][1];
            sm1 += sa[j][2] + sa[j][3];
        }
        sm0 = redsum4(sm0); sm1 = redsum4(sm1);
        rl0 = rl0 * al0 + sm0;
        rl1 = rl1 * al1 + sm1;
        #pragma unroll
        for (int nt = 0; nt < 8; nt++) {
            O[nt][0] *= al0; O[nt][1] *= al0;
            O[nt][2] *= al1; O[nt][3] *= al1;
        }

        // ---- O += P V ----
        const uint32_t vb0 = stb + voff0;
        #pragma unroll
        for (int kk = 0; kk < 8; kk++) {
            uint32_t p0 = hpack(sa[2 * kk][0],     sa[2 * kk][1]);
            uint32_t p1 = hpack(sa[2 * kk][2],     sa[2 * kk][3]);
            uint32_t p2 = hpack(sa[2 * kk + 1][0], sa[2 * kk + 1][1]);
            uint32_t p3 = hpack(sa[2 * kk + 1][2], sa[2 * kk + 1][3]);
            const uint32_t vbk = vb0 + (uint32_t)(kk * 2048);
            #pragma unroll
            for (int pd = 0; pd < 4; pd++) {
                uint32_t v0, v1, v2, v3;
                ldsm4t(v0, v1, v2, v3, vbk ^ (uint32_t)(pd * 32));
                mma16816(O[2 * pd],     p0, p1, p2, p3, v0, v1);
                mma16816(O[2 * pd + 1], p0, p1, p2, p3, v2, v3);
            }
        }
        __syncthreads();
        if (t + 2 < 8 && tid == 0) load_kv(s, t + 2);
    }

    // normalize; write z (single fp16) into tiled/swizzled proj A-blocks.
    float inv0 = 1.0f / rl0, inv1 = 1.0f / rl1;
    const int b = bh >> 4, h = bh & 15;
    const int t0 = qb * 128 + w * 16 + (lane >> 2);
    const int cq = (lane & 3) * 2;
    #pragma unroll
    for (int nt = 0; nt < 8; nt++) {
        int kk = nt * 8 + cq;
        #pragma unroll
        for (int e = 0; e < 2; e++) {
            int m = b * NTOK + t0 + e * 8;
            int mb2 = m >> 7, r = m & 127;
            size_t base = ((size_t)mb2 * 16 + h) * 16384;
            uint32_t sw = swz128((uint32_t)(r * 128 + kk * 2));
            float inv = e ? inv1 : inv0;
            __half2 zz = __floats2half2_rn(O[nt][2 * e] * inv, O[nt][2 * e + 1] * inv);
            *(__half2*)((char*)g_zh + base + sw) = zz;
        }
    }
}

// ---------------------------------------------------------------------------
extern "C" void kernel_launch(void* const* d_in, const int* in_sizes, int n_in,
                              void* d_out, int out_size)
{
    const float* x      = (const float*)d_in[0];
    const float* qkv_w  = (const float*)d_in[1];
    const float* qkv_b  = (const float*)d_in[2];
    const float* proj_w = (const float*)d_in[3];
    const float* proj_b = (const float*)d_in[4];
    float* out = (float*)d_out;

    const int M = B_SZ * NTOK;

    cudaFuncSetAttribute(mma_attn, cudaFuncAttributeMaxDynamicSharedMemorySize, 81920);
    cudaFuncSetAttribute(blk_gemm<0>, cudaFuncAttributeMaxDynamicSharedMemorySize, 65536);
    cudaFuncSetAttribute(blk_gemm<1>, cudaFuncAttributeMaxDynamicSharedMemorySize, 65536);

    __half *xh, *qwh, *pwh, *zh;
    cudaGetSymbolAddress((void**)&xh,  g_xh);
    cudaGetSymbolAddress((void**)&qwh, g_qwh);
    cudaGetSymbolAddress((void**)&pwh, g_pwh);
    cudaGetSymbolAddress((void**)&zh,  g_zh);

    dim3 blk(256);

    // 0) coalesced round of x + both weights
    round_coal<<<1536, blk>>>(x, qkv_w, proj_w, xh, qwh, pwh);

    // 1) QKV GEMM -> q/k/v single fp16 swizzled chunks (q pre-scaled by QSCALE)
    blk_gemm<0><<<dim3(3 * DMODEL / 128, M / 128), blk, 65536>>>(
        xh, qwh, qkv_b, nullptr);

    // 2) Flash attention -> z single fp16
    mma_attn<<<dim3(NTOK / 128, B_SZ * NHEAD), blk, 81920>>>();

    // 3) Output projection -> out fp32
    blk_gemm<1><<<dim3(DMODEL / 128, M / 128), blk, 65536>>>(
        zh, pwh, proj_b, out);
}